// round 7
// baseline (speedup 1.0000x reference)
#include <cuda_runtime.h>
#include <cstdint>
#include <cstddef>

// Sparsemax (alpha=2), persistent CTAs + double-buffered async bulk prefetch.
// Per row: the first 48KB arrives via cp.async.bulk into smem (issued 1-2 rows
// ahead, overlapping the previous row's gather/tau/store phases); the
// remaining ~77KB is LDG-streamed and stays L2-resident for the re-reads.
// Candidate set {x > rowmax-1} is a superset of everything that can
// contribute to the reference bisection's f(tau) (every iterate > rowmax-1).
// tau: closed-form sorted-threshold rule for K<=32 (typical K ~ 8-30),
// reference bisection over candidates for K<=512, full-row bisection fallback.

#define SPM_D   32000
#define SPM_D4  (SPM_D / 4)          // 8000 float4
#define SPM_C4  3072                 // prefetched float4 per row (48KB)
#define SPM_R4  (SPM_D4 - SPM_C4)    // 4928 float4 via LDG (L2-resident)
#define SPM_NT  512
#define SPM_NW  (SPM_NT / 32)
#define FCAP    512
#define BULK_BYTES (SPM_C4 * 16)     // 49152

#define NEG_INF (-3.402823466e38f)
#define FULL    0xffffffffu

__device__ __forceinline__ float warp_max(float v) {
#pragma unroll
    for (int o = 16; o; o >>= 1) v = fmaxf(v, __shfl_xor_sync(FULL, v, o));
    return v;
}
__device__ __forceinline__ float warp_sum(float v) {
#pragma unroll
    for (int o = 16; o; o >>= 1) v += __shfl_xor_sync(FULL, v, o);
    return v;
}

__device__ __forceinline__ uint32_t smem_u32(const void* p) {
    uint32_t a;
    asm("{ .reg .u64 t; cvta.to.shared.u64 t, %1; cvt.u32.u64 %0, t; }"
        : "=r"(a) : "l"(p));
    return a;
}
__device__ __forceinline__ void mbar_init(uint32_t mbar, uint32_t cnt) {
    asm volatile("mbarrier.init.shared.b64 [%0], %1;" :: "r"(mbar), "r"(cnt) : "memory");
}
__device__ __forceinline__ void mbar_expect_tx(uint32_t mbar, uint32_t bytes) {
    asm volatile("mbarrier.arrive.expect_tx.shared.b64 _, [%0], %1;"
                 :: "r"(mbar), "r"(bytes) : "memory");
}
__device__ __forceinline__ void mbar_wait(uint32_t mbar, uint32_t parity) {
    asm volatile(
        "{\n\t.reg .pred P;\n\t"
        "W_%=:\n\t"
        "mbarrier.try_wait.parity.acquire.cta.shared::cta.b64 P, [%0], %1, 0x989680;\n\t"
        "@P bra D_%=;\n\t"
        "bra W_%=;\n\t"
        "D_%=:\n\t}"
        :: "r"(mbar), "r"(parity) : "memory");
}
__device__ __forceinline__ void bulk_g2s(uint32_t dst, const void* src,
                                         uint32_t bytes, uint32_t mbar) {
    asm volatile(
        "cp.async.bulk.shared::cta.global.mbarrier::complete_tx::bytes "
        "[%0], [%1], %2, [%3];"
        :: "r"(dst), "l"(src), "r"(bytes), "r"(mbar) : "memory");
}

extern __shared__ float4 s_buf[];    // [2][SPM_C4] = 96KB

__global__ __launch_bounds__(SPM_NT, 2)
void spm_kernel(const float* __restrict__ X, float* __restrict__ Y, int rows) {
    __shared__ float s_filt[FCAP];
    __shared__ float s_wmax[SPM_NW];
    __shared__ float s_r[SPM_NW];
    __shared__ int   s_K;
    __shared__ float s_tau, s_inv;
    __shared__ __align__(8) uint64_t s_mbar[2];

    const int tid  = threadIdx.x;
    const int lane = tid & 31;
    const int wid  = tid >> 5;
    const int stride = gridDim.x;
    const float inv_d = 1.0f / (float)SPM_D;

    const uint32_t mb0 = smem_u32(&s_mbar[0]);
    const uint32_t mb1 = smem_u32(&s_mbar[1]);
    const uint32_t buf_u32[2] = { smem_u32(&s_buf[0]), smem_u32(&s_buf[SPM_C4]) };

    if (tid == 0) { mbar_init(mb0, 1); mbar_init(mb1, 1); }
    __syncthreads();

    // Prologue: prefetch cached portions of first two assigned rows
    if (tid == 0) {
        long r0 = blockIdx.x;
        if (r0 < rows) {
            mbar_expect_tx(mb0, BULK_BYTES);
            bulk_g2s(buf_u32[0], X + r0 * (long)SPM_D, BULK_BYTES, mb0);
        }
        long r1 = r0 + stride;
        if (r1 < rows) {
            mbar_expect_tx(mb1, BULK_BYTES);
            bulk_g2s(buf_u32[1], X + r1 * (long)SPM_D, BULK_BYTES, mb1);
        }
    }

    int ph[2] = {0, 0};
    int k = 0;
    for (long row = blockIdx.x; row < rows; row += stride, ++k) {
        const int b = k & 1;
        const uint32_t mb = b ? mb1 : mb0;
        float4* buf = s_buf + (size_t)b * SPM_C4;

        const float4* __restrict__ x4 =
            reinterpret_cast<const float4*>(X + row * (long)SPM_D);
        float4* __restrict__ y4 =
            reinterpret_cast<float4*>(Y + row * (long)SPM_D);

        if (tid == 0) s_K = 0;

        // ---- P1: LDG-stream non-cached tail (stays L2) + max ----
        float mx = NEG_INF;
#pragma unroll 4
        for (int i = tid; i < SPM_R4; i += SPM_NT) {
            float4 v = x4[SPM_C4 + i];
            mx = fmaxf(mx, fmaxf(fmaxf(v.x, v.y), fmaxf(v.z, v.w)));
        }
        // wait prefetched head, fold its max in
        mbar_wait(mb, ph[b]); ph[b] ^= 1;
#pragma unroll 4
        for (int i = tid; i < SPM_C4; i += SPM_NT) {
            float4 v = buf[i];
            mx = fmaxf(mx, fmaxf(fmaxf(v.x, v.y), fmaxf(v.z, v.w)));
        }
        mx = warp_max(mx);
        if (lane == 0) s_wmax[wid] = mx;
        __syncthreads();                       // also orders s_K reset

        float m = (lane < SPM_NW) ? s_wmax[lane] : NEG_INF;
        const float mxv  = warp_max(m);        // block max, redundant per warp
        const float thrF = mxv - 1.0f;

        // ---- P2: gather candidates > rowmax-1 (rare-hit atomics) ----
#pragma unroll 2
        for (int i = tid; i < SPM_C4; i += SPM_NT) {
            float4 v = buf[i];
            if (v.x > thrF) { int p = atomicAdd(&s_K, 1); if (p < FCAP) s_filt[p] = v.x; }
            if (v.y > thrF) { int p = atomicAdd(&s_K, 1); if (p < FCAP) s_filt[p] = v.y; }
            if (v.z > thrF) { int p = atomicAdd(&s_K, 1); if (p < FCAP) s_filt[p] = v.z; }
            if (v.w > thrF) { int p = atomicAdd(&s_K, 1); if (p < FCAP) s_filt[p] = v.w; }
        }
#pragma unroll 2
        for (int i = tid; i < SPM_R4; i += SPM_NT) {
            float4 v = __ldcg(&x4[SPM_C4 + i]);
            if (v.x > thrF) { int p = atomicAdd(&s_K, 1); if (p < FCAP) s_filt[p] = v.x; }
            if (v.y > thrF) { int p = atomicAdd(&s_K, 1); if (p < FCAP) s_filt[p] = v.y; }
            if (v.z > thrF) { int p = atomicAdd(&s_K, 1); if (p < FCAP) s_filt[p] = v.z; }
            if (v.w > thrF) { int p = atomicAdd(&s_K, 1); if (p < FCAP) s_filt[p] = v.w; }
        }
        __syncthreads();
        const int K = s_K;                     // uniform; K >= 1 always

        float tau, inv;
        bool need_full = false;

        if (K <= 32) {
            // ---- Closed-form threshold, redundant per-warp ----
            float z = (lane < K) ? s_filt[lane] : NEG_INF;
#pragma unroll
            for (int kk = 2; kk <= 32; kk <<= 1) {
#pragma unroll
                for (int j = kk >> 1; j > 0; j >>= 1) {
                    float o = __shfl_xor_sync(FULL, z, j);
                    bool lower   = (lane & j) == 0;
                    bool descBlk = (lane & kk) == 0;
                    z = (lower == descBlk) ? fmaxf(z, o) : fminf(z, o);
                }
            }
            float S = z;
#pragma unroll
            for (int o = 1; o < 32; o <<= 1) {
                float t = __shfl_up_sync(FULL, S, o);
                if (lane >= o) S += t;
            }
            float kf = (float)(lane + 1);
            unsigned bal = __ballot_sync(FULL, fmaf(kf, z, 1.0f) > S);
            int h = 31 - __clz(bal);
            tau = __shfl_sync(FULL, (S - 1.0f) / kf, h);
            float s = warp_sum(fmaxf(z - tau, 0.0f));
            inv = 1.0f / s;
        } else if (K <= FCAP) {
            // ---- Reference bisection over candidates (warp 0) ----
            if (wid == 0) {
                float tlo = thrF;
                float dm  = (mxv - inv_d) - tlo;
                float a = 0.0f;
                for (int i = lane; i < K; i += 32)
                    a += fmaxf(s_filt[i] - tlo, 0.0f);
                const float flo = warp_sum(a) - 1.0f;
                float tm = tlo, fm = flo;
                for (int it = 0; it < 50; ++it) {
                    dm *= 0.5f;
                    tm = tlo + dm;
                    float s = 0.0f;
                    for (int i = lane; i < K; i += 32)
                        s += fmaxf(s_filt[i] - tm, 0.0f);
                    fm = warp_sum(s) - 1.0f;
                    if (fm * flo >= 0.0f) tlo = tm;
                }
                if (lane == 0) { s_tau = tm; s_inv = 1.0f / (fm + 1.0f); }
            }
            __syncthreads();
            tau = s_tau; inv = s_inv;
        } else {
            need_full = true;
            tau = 0.0f; inv = 1.0f;
        }

        if (need_full) {
            // ---- Correctness fallback: block bisection, smem + L2 row ----
            float tlo = thrF;
            float dm  = (mxv - inv_d) - tlo;

            float a = 0.0f;
            for (int i = tid; i < SPM_D4; i += SPM_NT) {
                float4 v = (i < SPM_C4) ? buf[i] : __ldcg(&x4[i]);
                a += fmaxf(v.x - tlo, 0.0f) + fmaxf(v.y - tlo, 0.0f) +
                     fmaxf(v.z - tlo, 0.0f) + fmaxf(v.w - tlo, 0.0f);
            }
            a = warp_sum(a);
            if (lane == 0) s_r[wid] = a;
            __syncthreads();
            float r0 = (lane < SPM_NW) ? s_r[lane] : 0.0f;
            const float flo = warp_sum(r0) - 1.0f;

            float tm = tlo, fm = flo;
            for (int it = 0; it < 50; ++it) {
                dm *= 0.5f;
                tm = tlo + dm;
                float s = 0.0f;
                for (int i = tid; i < SPM_D4; i += SPM_NT) {
                    float4 v = (i < SPM_C4) ? buf[i] : __ldcg(&x4[i]);
                    s += fmaxf(v.x - tm, 0.0f) + fmaxf(v.y - tm, 0.0f) +
                         fmaxf(v.z - tm, 0.0f) + fmaxf(v.w - tm, 0.0f);
                }
                s = warp_sum(s);
                __syncthreads();
                if (lane == 0) s_r[wid] = s;
                __syncthreads();
                float rr = (lane < SPM_NW) ? s_r[lane] : 0.0f;
                fm = warp_sum(rr) - 1.0f;
                if (fm * flo >= 0.0f) tlo = tm;
            }
            tau = tm;
            inv = 1.0f / (fm + 1.0f);
        }

        // ---- P3: smem + L2 re-read, streaming writes ----
#pragma unroll 4
        for (int i = tid; i < SPM_C4; i += SPM_NT) {
            float4 v = buf[i];
            float4 r;
            r.x = fmaxf(v.x - tau, 0.0f) * inv;
            r.y = fmaxf(v.y - tau, 0.0f) * inv;
            r.z = fmaxf(v.z - tau, 0.0f) * inv;
            r.w = fmaxf(v.w - tau, 0.0f) * inv;
            __stcs(&y4[i], r);
        }
#pragma unroll 4
        for (int i = tid; i < SPM_R4; i += SPM_NT) {
            float4 v = __ldcg(&x4[SPM_C4 + i]);
            float4 r;
            r.x = fmaxf(v.x - tau, 0.0f) * inv;
            r.y = fmaxf(v.y - tau, 0.0f) * inv;
            r.z = fmaxf(v.z - tau, 0.0f) * inv;
            r.w = fmaxf(v.w - tau, 0.0f) * inv;
            __stcs(&y4[SPM_C4 + i], r);
        }

        __syncthreads();   // all threads done reading buf b -> safe to refill

        // Prefetch row (k+2) into this buffer (overlaps next row's phases)
        if (tid == 0) {
            long rn = row + 2L * stride;
            if (rn < rows) {
                mbar_expect_tx(mb, BULK_BYTES);
                bulk_g2s(buf_u32[b], X + rn * (long)SPM_D, BULK_BYTES, mb);
            }
        }
    }
}

extern "C" void kernel_launch(void* const* d_in, const int* in_sizes, int n_in,
                              void* d_out, int out_size) {
    const float* X = (const float*)d_in[0];
    float* Y       = (float*)d_out;
    const int rows = in_sizes[0] / SPM_D;

    int dev = 0, sms = 148;
    cudaGetDevice(&dev);
    cudaDeviceGetAttribute(&sms, cudaDevAttrMultiProcessorCount, dev);

    const int shmem = 2 * SPM_C4 * sizeof(float4);   // 96KB
    cudaFuncSetAttribute(spm_kernel,
                         cudaFuncAttributeMaxDynamicSharedMemorySize, shmem);

    int grid = 2 * sms;
    if (grid > rows) grid = rows;
    spm_kernel<<<grid, SPM_NT, shmem>>>(X, Y, rows);
}

// round 8
// speedup vs baseline: 1.4233x; 1.4233x over previous
#include <cuda_runtime.h>
#include <cstddef>

// Sparsemax (alpha=2), 3 CTAs/SM, 72KB smem row cache, register-max gather.
// P1: stream row once (DRAM): 72KB -> smem (__ldcs), 54KB via default LDG
//     (stays L2-resident). Each thread tracks block-max contribution PLUS two
//     private maxima (cached-region / tail-region elements it owns).
// P2: thrF = rowmax-1. A thread rescans its own elements only if its private
//     max exceeds thrF => exact candidate set {x > thrF} with ~zero memory
//     traffic (candidates are ~8-30 per row of 32000).
//     (Every reference bisection iterate > rowmax-1, so all other elements
//     contribute 0 to f(tau); candidate-only computation is exact.)
// tau: closed-form sorted-threshold rule for K<=32, computed redundantly in
//     every warp; reference bisection over candidates for K<=512; full-row
//     block bisection as overflow fallback.
// P3: smem + L2 re-read, streaming stores.

#define SPM_D   32000
#define SPM_D4  (SPM_D / 4)      // 8000 float4
#define SPM_C4  4608             // cached float4 (72KB) = 9 * 512
#define SPM_NT  512
#define SPM_NW  (SPM_NT / 32)    // 16 warps
#define N_CIT   (SPM_C4 / SPM_NT)            // 9 cached iters
#define SPM_T4  (SPM_D4 - SPM_C4)            // 3392 tail float4
#define N_TIT   ((SPM_T4 + SPM_NT - 1) / SPM_NT)  // 7 tail iters (last partial)
#define FCAP    512

#define NEG_INF (-3.402823466e38f)
#define FULL    0xffffffffu

__device__ __forceinline__ float warp_max(float v) {
#pragma unroll
    for (int o = 16; o; o >>= 1) v = fmaxf(v, __shfl_xor_sync(FULL, v, o));
    return v;
}
__device__ __forceinline__ float warp_sum(float v) {
#pragma unroll
    for (int o = 16; o; o >>= 1) v += __shfl_xor_sync(FULL, v, o);
    return v;
}

extern __shared__ float4 s_x4[];   // SPM_C4 float4 = 72KB

__global__ __launch_bounds__(SPM_NT, 3)
void spm_kernel(const float* __restrict__ X, float* __restrict__ Y) {
    __shared__ float s_filt[FCAP];
    __shared__ float s_wmax[SPM_NW];
    __shared__ float s_r[SPM_NW];
    __shared__ int   s_K;
    __shared__ float s_tau, s_inv;

    const int tid  = threadIdx.x;
    const int lane = tid & 31;
    const int wid  = tid >> 5;
    const int row  = blockIdx.x;

    const float4* __restrict__ x4 =
        reinterpret_cast<const float4*>(X + (size_t)row * (size_t)SPM_D);
    float4* __restrict__ y4 =
        reinterpret_cast<float4*>(Y + (size_t)row * (size_t)SPM_D);

    if (tid == 0) s_K = 0;

    // ---- P1: stream row; cache head in smem; private region maxima ----
    float mxc = NEG_INF;   // max over this thread's cached elements
    float mxt = NEG_INF;   // max over this thread's tail elements
#pragma unroll
    for (int j = 0; j < N_CIT; ++j) {
        const int i = j * SPM_NT + tid;
        float4 v = __ldcs(&x4[i]);            // smem-cached; skip L2 reuse
        s_x4[i] = v;
        mxc = fmaxf(mxc, fmaxf(fmaxf(v.x, v.y), fmaxf(v.z, v.w)));
    }
#pragma unroll
    for (int j = 0; j < N_TIT; ++j) {
        const int i = SPM_C4 + j * SPM_NT + tid;
        if (i < SPM_D4) {
            float4 v = x4[i];                 // default: keep in L2
            mxt = fmaxf(mxt, fmaxf(fmaxf(v.x, v.y), fmaxf(v.z, v.w)));
        }
    }
    float mx = warp_max(fmaxf(mxc, mxt));
    if (lane == 0) s_wmax[wid] = mx;
    __syncthreads();                           // barrier 1 (orders s_K too)

    float m = (lane < SPM_NW) ? s_wmax[lane] : NEG_INF;
    const float mxv   = warp_max(m);           // block max, redundant per warp
    const float thrF  = mxv - 1.0f;
    const float inv_d = 1.0f / (float)SPM_D;

    // ---- P2: exact candidate gather via private-max guard (rare path) ----
    if (mxc > thrF) {
#pragma unroll
        for (int j = 0; j < N_CIT; ++j) {
            const int i = j * SPM_NT + tid;
            float4 v = s_x4[i];
            if (v.x > thrF) { int p = atomicAdd(&s_K, 1); if (p < FCAP) s_filt[p] = v.x; }
            if (v.y > thrF) { int p = atomicAdd(&s_K, 1); if (p < FCAP) s_filt[p] = v.y; }
            if (v.z > thrF) { int p = atomicAdd(&s_K, 1); if (p < FCAP) s_filt[p] = v.z; }
            if (v.w > thrF) { int p = atomicAdd(&s_K, 1); if (p < FCAP) s_filt[p] = v.w; }
        }
    }
    if (mxt > thrF) {
#pragma unroll
        for (int j = 0; j < N_TIT; ++j) {
            const int i = SPM_C4 + j * SPM_NT + tid;
            if (i < SPM_D4) {
                float4 v = __ldcg(&x4[i]);     // L2 hit
                if (v.x > thrF) { int p = atomicAdd(&s_K, 1); if (p < FCAP) s_filt[p] = v.x; }
                if (v.y > thrF) { int p = atomicAdd(&s_K, 1); if (p < FCAP) s_filt[p] = v.y; }
                if (v.z > thrF) { int p = atomicAdd(&s_K, 1); if (p < FCAP) s_filt[p] = v.z; }
                if (v.w > thrF) { int p = atomicAdd(&s_K, 1); if (p < FCAP) s_filt[p] = v.w; }
            }
        }
    }
    __syncthreads();                           // barrier 2
    const int K = s_K;                         // uniform; K >= 1 always

    float tau, inv;
    bool need_full = false;

    if (K <= 32) {
        // ---- Closed-form threshold, redundant per-warp (no barrier) ----
        float z = (lane < K) ? s_filt[lane] : NEG_INF;
        // bitonic sort, descending
#pragma unroll
        for (int kk = 2; kk <= 32; kk <<= 1) {
#pragma unroll
            for (int j = kk >> 1; j > 0; j >>= 1) {
                float o = __shfl_xor_sync(FULL, z, j);
                bool lower   = (lane & j) == 0;
                bool descBlk = (lane & kk) == 0;
                z = (lower == descBlk) ? fmaxf(z, o) : fminf(z, o);
            }
        }
        // inclusive prefix sum
        float S = z;
#pragma unroll
        for (int o = 1; o < 32; o <<= 1) {
            float t = __shfl_up_sync(FULL, S, o);
            if (lane >= o) S += t;
        }
        float kf = (float)(lane + 1);
        unsigned bal = __ballot_sync(FULL, fmaf(kf, z, 1.0f) > S);
        int h = 31 - __clz(bal);               // lane 0 always qualifies
        tau = __shfl_sync(FULL, (S - 1.0f) / kf, h);
        float s = warp_sum(fmaxf(z - tau, 0.0f));
        inv = 1.0f / s;
    } else if (K <= FCAP) {
        // ---- Reference bisection over candidates (warp 0) ----
        if (wid == 0) {
            float tlo = thrF;
            float dm  = (mxv - inv_d) - tlo;
            float a = 0.0f;
            for (int i = lane; i < K; i += 32)
                a += fmaxf(s_filt[i] - tlo, 0.0f);
            const float flo = warp_sum(a) - 1.0f;
            float tm = tlo, fm = flo;
            for (int it = 0; it < 50; ++it) {
                dm *= 0.5f;
                tm = tlo + dm;
                float s = 0.0f;
                for (int i = lane; i < K; i += 32)
                    s += fmaxf(s_filt[i] - tm, 0.0f);
                fm = warp_sum(s) - 1.0f;
                if (fm * flo >= 0.0f) tlo = tm;
            }
            if (lane == 0) { s_tau = tm; s_inv = 1.0f / (fm + 1.0f); }
        }
        __syncthreads();
        tau = s_tau; inv = s_inv;
    } else {
        need_full = true;                       // uniform
        tau = 0.0f; inv = 1.0f;
    }

    if (need_full) {
        // ---- Correctness fallback: block bisection, smem + L2 row ----
        float tlo = thrF;
        float dm  = (mxv - inv_d) - tlo;

        float a = 0.0f;
        for (int i = tid; i < SPM_D4; i += SPM_NT) {
            float4 v = (i < SPM_C4) ? s_x4[i] : __ldcg(&x4[i]);
            a += fmaxf(v.x - tlo, 0.0f) + fmaxf(v.y - tlo, 0.0f) +
                 fmaxf(v.z - tlo, 0.0f) + fmaxf(v.w - tlo, 0.0f);
        }
        a = warp_sum(a);
        if (lane == 0) s_r[wid] = a;
        __syncthreads();
        float r0 = (lane < SPM_NW) ? s_r[lane] : 0.0f;
        const float flo = warp_sum(r0) - 1.0f;

        float tm = tlo, fm = flo;
        for (int it = 0; it < 50; ++it) {
            dm *= 0.5f;
            tm = tlo + dm;
            float s = 0.0f;
            for (int i = tid; i < SPM_D4; i += SPM_NT) {
                float4 v = (i < SPM_C4) ? s_x4[i] : __ldcg(&x4[i]);
                s += fmaxf(v.x - tm, 0.0f) + fmaxf(v.y - tm, 0.0f) +
                     fmaxf(v.z - tm, 0.0f) + fmaxf(v.w - tm, 0.0f);
            }
            s = warp_sum(s);
            __syncthreads();
            if (lane == 0) s_r[wid] = s;
            __syncthreads();
            float rr = (lane < SPM_NW) ? s_r[lane] : 0.0f;
            fm = warp_sum(rr) - 1.0f;
            if (fm * flo >= 0.0f) tlo = tm;
        }
        tau = tm;
        inv = 1.0f / (fm + 1.0f);
    }

    // ---- P3: smem + L2 re-read, streaming writes ----
#pragma unroll
    for (int j = 0; j < N_CIT; ++j) {
        const int i = j * SPM_NT + tid;
        float4 v = s_x4[i];
        float4 r;
        r.x = fmaxf(v.x - tau, 0.0f) * inv;
        r.y = fmaxf(v.y - tau, 0.0f) * inv;
        r.z = fmaxf(v.z - tau, 0.0f) * inv;
        r.w = fmaxf(v.w - tau, 0.0f) * inv;
        __stcs(&y4[i], r);
    }
#pragma unroll
    for (int j = 0; j < N_TIT; ++j) {
        const int i = SPM_C4 + j * SPM_NT + tid;
        if (i < SPM_D4) {
            float4 v = __ldcg(&x4[i]);
            float4 r;
            r.x = fmaxf(v.x - tau, 0.0f) * inv;
            r.y = fmaxf(v.y - tau, 0.0f) * inv;
            r.z = fmaxf(v.z - tau, 0.0f) * inv;
            r.w = fmaxf(v.w - tau, 0.0f) * inv;
            __stcs(&y4[i], r);
        }
    }
}

extern "C" void kernel_launch(void* const* d_in, const int* in_sizes, int n_in,
                              void* d_out, int out_size) {
    const float* X = (const float*)d_in[0];
    float* Y       = (float*)d_out;
    const int rows = in_sizes[0] / SPM_D;
    const int shmem = SPM_C4 * sizeof(float4);  // 72KB

    cudaFuncSetAttribute(spm_kernel,
                         cudaFuncAttributeMaxDynamicSharedMemorySize, shmem);
    spm_kernel<<<rows, SPM_NT, shmem>>>(X, Y);
}